// round 15
// baseline (speedup 1.0000x reference)
#include <cuda_runtime.h>
#include <cuda_bf16.h>
#include <cuda_fp16.h>
#include <math.h>
#include <stdint.h>

// Problem constants
#define BATCH 4
#define SEQ   2048
#define CDIM  1024
#define HEADS 16
#define HD    64
#define M_ROWS (BATCH * SEQ)          // 8192
#define QKV_N  (3 * CDIM)             // 3072
#define KDIM   CDIM
#define BHN    ((size_t)BATCH * HEADS * SEQ)

// 0.125 * log2(e)
#define FA_SCALE 0.18033688011112042f

// -------- scratch (allocation-free: __device__ globals) ----------
// f16 attention operands, [B,H,N,hd]
__device__ __half g_qh[BHN * HD];
__device__ __half g_kh[BHN * HD];
__device__ __half g_vh[BHN * HD];

// f16 operands for dense GEMMs
__device__ __half g_x16[(size_t)M_ROWS * KDIM];
__device__ __half g_wq16[(size_t)QKV_N * KDIM];
__device__ __half g_wp16[(size_t)CDIM * KDIM];
__device__ __half g_ao16[(size_t)M_ROWS * CDIM];

// ================= helpers ==================================
__device__ __forceinline__ uint32_t smem_u32(const void* p) {
    uint32_t a;
    asm("{ .reg .u64 t; cvta.to.shared.u64 t, %1; cvt.u32.u64 %0, t; }"
        : "=r"(a) : "l"(p));
    return a;
}
__device__ __forceinline__ void cp_async16(uint32_t dst, const void* src) {
    asm volatile("cp.async.cg.shared.global [%0], [%1], 16;" :: "r"(dst), "l"(src));
}
#define CP_ASYNC_COMMIT() asm volatile("cp.async.commit_group;" ::: "memory")
#define CP_ASYNC_WAIT(N)  asm volatile("cp.async.wait_group %0;" :: "n"(N) : "memory")

#define LDMATRIX_X4(r, addr) \
    asm volatile("ldmatrix.sync.aligned.m8n8.x4.shared.b16 {%0,%1,%2,%3}, [%4];" \
        : "=r"((r)[0]), "=r"((r)[1]), "=r"((r)[2]), "=r"((r)[3]) \
        : "r"(addr))
#define LDMATRIX_X4_T(r, addr) \
    asm volatile("ldmatrix.sync.aligned.m8n8.x4.trans.shared.b16 {%0,%1,%2,%3}, [%4];" \
        : "=r"((r)[0]), "=r"((r)[1]), "=r"((r)[2]), "=r"((r)[3]) \
        : "r"(addr))

__device__ __forceinline__ void mma_f16(float* c, const uint32_t* a,
                                        uint32_t b0, uint32_t b1) {
    asm volatile(
        "mma.sync.aligned.m16n8k16.row.col.f32.f16.f16.f32 "
        "{%0,%1,%2,%3}, {%4,%5,%6,%7}, {%8,%9}, {%0,%1,%2,%3};"
        : "+f"(c[0]), "+f"(c[1]), "+f"(c[2]), "+f"(c[3])
        : "r"(a[0]), "r"(a[1]), "r"(a[2]), "r"(a[3]), "r"(b0), "r"(b1));
}

__device__ __forceinline__ float ex2f(float x) {
    float r; asm("ex2.approx.ftz.f32 %0, %1;" : "=f"(r) : "f"(x)); return r;
}
__device__ __forceinline__ uint32_t ex2_pk(float lo, float hi) {
    uint32_t p, r;
    asm("cvt.rn.f16x2.f32 %0, %1, %2;" : "=r"(p) : "f"(hi), "f"(lo));
    asm("ex2.approx.f16x2 %0, %1;" : "=r"(r) : "r"(p));
    return r;
}

// =================================================================
// cvt: fp32 -> f16 (single)
// =================================================================
__global__ __launch_bounds__(256) void cvt_f16(
    const float* __restrict__ in, __half* __restrict__ out, size_t n)
{
    size_t i = ((size_t)blockIdx.x * blockDim.x + threadIdx.x) * 4;
    if (i >= n) return;
    float4 v = *(const float4*)&in[i];
    __half2 p0 = {__float2half_rn(v.x), __float2half_rn(v.y)};
    __half2 p1 = {__float2half_rn(v.z), __float2half_rn(v.w)};
    *(uint2*)&out[i] = make_uint2(*(uint32_t*)&p0, *(uint32_t*)&p1);
}

// =================================================================
// Shared GEMM mainloop macro pieces (BM=BN=128, BK=64, 256 thr,
// 8 warps x (16 rows x 128 cols), A register-resident, 2-stage).
// =================================================================
#define G1_ROW_B   144
#define G1_TILE_B  (128 * G1_ROW_B)       // 18432
#define G1_STAGE_B (2 * G1_TILE_B)        // 36864 (A, W)
#define G1_SMEM_B  (2 * G1_STAGE_B)       // 73728

#define GEMM_MAINLOOP(ACC, A_PTR, W_PTR)                                      \
    const uint32_t sbase = smem_u32(smem);                                    \
    const int tid  = threadIdx.x;                                             \
    const int wid  = tid >> 5;                                                \
    const int lane = tid & 31;                                                \
    const int m0 = blockIdx.y * 128;                                          \
    const int n0 = blockIdx.x * 128;                                          \
    const __half* tbA = (A_PTR) + (size_t)m0 * K;                             \
    const __half* tbW = (W_PTR) + (size_t)n0 * K;                             \
    const int KITERS = K >> 6;                                                \
    auto load_stage = [&](int it, uint32_t stage) {                           \
        const int k0 = it << 6;                                               \
        _Pragma("unroll")                                                     \
        for (int j = 0; j < 8; j++) {                                         \
            int c    = tid + j * 256;                                         \
            int tile = c >> 10;                                               \
            int r    = (c >> 3) & 127;                                        \
            int g    = c & 7;                                                 \
            const __half* src = (tile ? tbW : tbA) + (size_t)r * K + k0 + g * 8; \
            uint32_t dst = stage + tile * G1_TILE_B + r * G1_ROW_B + g * 16;  \
            cp_async16(dst, src);                                             \
        }                                                                     \
        CP_ASYNC_COMMIT();                                                    \
    };                                                                        \
    _Pragma("unroll")                                                         \
    for (int i = 0; i < 8; i++)                                               \
        _Pragma("unroll")                                                     \
        for (int j = 0; j < 8; j++) ACC[i][j] = 0.f;                          \
    load_stage(0, sbase);                                                     \
    const int lrow  = lane & 15;                                              \
    const int khalf = lane >> 4;                                              \
    _Pragma("unroll 1")                                                       \
    for (int it = 0; it < KITERS; it++) {                                     \
        const uint32_t cur = sbase + (it & 1) * G1_STAGE_B;                   \
        if (it + 1 < KITERS) {                                                \
            load_stage(it + 1, sbase + ((it + 1) & 1) * G1_STAGE_B);          \
            CP_ASYNC_WAIT(1);                                                 \
        } else {                                                              \
            CP_ASYNC_WAIT(0);                                                 \
        }                                                                     \
        __syncthreads();                                                      \
        const uint32_t sA = cur;                                              \
        const uint32_t sW = cur + G1_TILE_B;                                  \
        _Pragma("unroll")                                                     \
        for (int ks = 0; ks < 4; ks++) {                                      \
            const int kbyte = ks * 32 + khalf * 16;                           \
            uint32_t a4[4];                                                   \
            LDMATRIX_X4(a4, sA + (uint32_t)(wid * 16 + lrow) * G1_ROW_B + kbyte); \
            _Pragma("unroll")                                                 \
            for (int bt = 0; bt < 8; bt++) {                                  \
                uint32_t b4[4];                                               \
                LDMATRIX_X4(b4, sW + (uint32_t)(bt * 16 + lrow) * G1_ROW_B + kbyte); \
                mma_f16(&ACC[bt][0], a4, b4[0], b4[2]);                       \
                mma_f16(&ACC[bt][4], a4, b4[1], b4[3]);                       \
            }                                                                 \
        }                                                                     \
        __syncthreads();                                                      \
    }

// =================================================================
// QKV GEMM with FUSED RMSNorm + RoPE + head-split epilogue.
// Output region (by n0): [0,1024)=Q, [1024,2048)=K, [2048,3072)=V.
// 128 cols = 2 complete heads; norm reduction = 2 shfl_xor over the
// 4-thread lane&3 group; rotate_half partner (d^32) = acc[bt^2].
// =================================================================
__global__ __launch_bounds__(256, 2) void gemm_qkv_fused(
    const __half* __restrict__ A, const __half* __restrict__ W,
    const float* __restrict__ cosb, const float* __restrict__ sinb,
    const float* __restrict__ qw, const float* __restrict__ kw,
    __half* __restrict__ Qh, __half* __restrict__ Kh, __half* __restrict__ Vh,
    int M, int N, int K)
{
    extern __shared__ __align__(128) char smem[];
    float acc[8][8];
    GEMM_MAINLOOP(acc, A, W)

    const unsigned FULL = 0xffffffffu;
    const int region = n0 >> 10;                 // 0 Q, 1 K, 2 V
    const int hbase  = (n0 & 1023) >> 6;         // first head in tile
    const int b      = m0 >> 11;                 // batch (128 | 2048)
    const int rl     = lane >> 2;

    if (region == 2) {
        // V: straight f32 -> f16, head-split store
#pragma unroll
        for (int rr = 0; rr < 2; rr++) {
            int row = m0 + wid * 16 + rl + rr * 8;
            int n   = row & (SEQ - 1);
            int rb  = rr * 2;
#pragma unroll
            for (int bt = 0; bt < 8; bt++) {
#pragma unroll
                for (int o = 0; o < 2; o++) {
                    int c = bt * 16 + o * 8 + (lane & 3) * 2;
                    int h = hbase + (c >> 6);
                    int d = c & 63;
                    __half2 hv = {__float2half_rn(acc[bt][o * 4 + rb]),
                                  __float2half_rn(acc[bt][o * 4 + rb + 1])};
                    *(__half2*)&Vh[(((size_t)(b * HEADS + h)) * SEQ + n) * HD + d] = hv;
                }
            }
        }
        return;
    }

    const float* wvec = (region == 0) ? qw : kw;
    __half* OutP = (region == 0) ? Qh : Kh;
    const float oscale = (region == 0) ? FA_SCALE : 1.0f;

#pragma unroll
    for (int rr = 0; rr < 2; rr++) {
        int row = m0 + wid * 16 + rl + rr * 8;
        int n   = row & (SEQ - 1);
        int rb  = rr * 2;
#pragma unroll
        for (int hh = 0; hh < 2; hh++) {
            // sum of squares over this head's 64 cols for this row
            float ss = 0.f;
#pragma unroll
            for (int bt4 = 0; bt4 < 4; bt4++) {
                int bt = hh * 4 + bt4;
#pragma unroll
                for (int o = 0; o < 2; o++) {
                    float v0 = acc[bt][o * 4 + rb];
                    float v1 = acc[bt][o * 4 + rb + 1];
                    ss += v0 * v0 + v1 * v1;
                }
            }
            ss += __shfl_xor_sync(FULL, ss, 1);
            ss += __shfl_xor_sync(FULL, ss, 2);
            float rinv = rsqrtf(ss * (1.0f / HD) + 1e-6f);
            int h = hbase + hh;
#pragma unroll
            for (int bt4 = 0; bt4 < 4; bt4++) {
                int bt = hh * 4 + bt4;
#pragma unroll
                for (int o = 0; o < 2; o++) {
                    int d = bt4 * 16 + o * 8 + (lane & 3) * 2;   // head-local
                    int dp = d ^ 32;
                    float2 wv  = *(const float2*)&wvec[d];
                    float2 wpv = *(const float2*)&wvec[dp];
                    float2 cv  = *(const float2*)&cosb[n * HD + d];
                    float2 sv  = *(const float2*)&sinb[n * HD + d];
                    float v0 = acc[bt][o * 4 + rb]     * rinv * wv.x;
                    float v1 = acc[bt][o * 4 + rb + 1] * rinv * wv.y;
                    float p0 = acc[bt ^ 2][o * 4 + rb]     * rinv * wpv.x;
                    float p1 = acc[bt ^ 2][o * 4 + rb + 1] * rinv * wpv.y;
                    float sgn = (d < 32) ? -1.f : 1.f;
                    float o0 = (v0 * cv.x + sgn * p0 * sv.x) * oscale;
                    float o1 = (v1 * cv.y + sgn * p1 * sv.y) * oscale;
                    __half2 hv = {__float2half_rn(o0), __float2half_rn(o1)};
                    *(__half2*)&OutP[(((size_t)(b * HEADS + h)) * SEQ + n) * HD + d] = hv;
                }
            }
        }
    }
}

// =================================================================
// Output projection GEMM: f32 out + bias.
// =================================================================
__global__ __launch_bounds__(256, 2) void gemm_proj(
    const __half* __restrict__ A, const __half* __restrict__ W,
    const float* __restrict__ bias, float* __restrict__ C,
    int M, int N, int K)
{
    extern __shared__ __align__(128) char smem[];
    float acc[8][8];
    GEMM_MAINLOOP(acc, A, W)

    int row0 = m0 + wid * 16 + (lane >> 2);
#pragma unroll
    for (int bt = 0; bt < 8; bt++) {
        int col = n0 + bt * 16 + (lane & 3) * 2;
#pragma unroll
        for (int o = 0; o < 2; o++) {
            int cc = col + o * 8;
            float b0 = bias[cc], b1 = bias[cc + 1];
            *(float2*)&C[(size_t)row0 * N + cc] =
                make_float2(acc[bt][o * 4 + 0] + b0, acc[bt][o * 4 + 1] + b1);
            *(float2*)&C[(size_t)(row0 + 8) * N + cc] =
                make_float2(acc[bt][o * 4 + 2] + b0, acc[bt][o * 4 + 3] + b1);
        }
    }
}

// =================================================================
// Flash attention, mma.sync f16, ONLINE-max softmax (R12 version).
// BQ=128 (8 warps x 16 rows), BK=64, hd=64. 2 CTAs/SM.
// =================================================================
#define FA_QSTRIDE 144
#define FA_KSTRIDE 144
#define FA_VSTRIDE 176
#define FA_OFF_QH  0
#define FA_STAGE0  (128 * FA_QSTRIDE)                 // 18432
#define FA_STG_K   0
#define FA_STG_V   (64 * FA_KSTRIDE)                  // 9216
#define FA_STAGE_B (64 * FA_KSTRIDE + 64 * FA_VSTRIDE)  // 20480
#define FA_SMEM    (FA_STAGE0 + 2 * FA_STAGE_B)       // 59392

__global__ __launch_bounds__(256, 2) void flash_attn_mma(
    const __half* __restrict__ Qh, const __half* __restrict__ Kh,
    const __half* __restrict__ Vh, __half* __restrict__ O)
{
    extern __shared__ __align__(128) char smem[];
    const uint32_t sb = smem_u32(smem);
    const unsigned FULL = 0xffffffffu;

    const int tid  = threadIdx.x;
    const int wid  = tid >> 5;
    const int lane = tid & 31;

    const int bh = blockIdx.y;
    const int b = bh >> 4, h = bh & 15;
    const int q0 = blockIdx.x * 128;
    const size_t qrow0 = (size_t)bh * SEQ + q0;
    const size_t krow0 = (size_t)bh * SEQ;

    for (int i = tid; i < 2 * 64 * 24; i += 256) {
        int cc = i % 24;
        int r  = (i / 24) & 63;
        int st = i / (24 * 64);
        __half val = (cc == 0) ? __float2half(1.0f) : __float2half(0.0f);
        *(__half*)(smem + FA_STAGE0 + st * FA_STAGE_B
                   + FA_STG_V + r * FA_VSTRIDE + (64 + cc) * 2) = val;
    }

#pragma unroll
    for (int j = 0; j < 4; j++) {
        int c = tid + j * 256;
        int r  = c >> 3;
        int g  = c & 7;
        cp_async16(sb + FA_OFF_QH + r * FA_QSTRIDE + g * 16,
                   Qh + (qrow0 + r) * HD + g * 8);
    }
    CP_ASYNC_COMMIT();

    auto load_kv = [&](int kt, uint32_t stg) {
        size_t rowbase = krow0 + (size_t)kt * 64;
#pragma unroll
        for (int j = 0; j < 4; j++) {
            int c = tid + j * 256;
            int t = c >> 9;
            int r = (c >> 3) & 63;
            int g = c & 7;
            const __half* src;
            uint32_t dst;
            if (t == 0) { src = Kh; dst = stg + FA_STG_K + r * FA_KSTRIDE + g * 16; }
            else        { src = Vh; dst = stg + FA_STG_V + r * FA_VSTRIDE + g * 16; }
            cp_async16(dst, src + (rowbase + r) * HD + g * 8);
        }
        CP_ASYNC_COMMIT();
    };

    load_kv(0, sb + FA_STAGE0);
    CP_ASYNC_WAIT(1);
    __syncthreads();

    uint32_t qfh[4][4];
    const int qb = wid * 16;
#pragma unroll
    for (int kc = 0; kc < 4; kc++) {
        uint32_t addr = sb + FA_OFF_QH + (uint32_t)(qb + (lane & 15)) * FA_QSTRIDE
                        + kc * 32 + (lane >> 4) * 16;
        LDMATRIX_X4(qfh[kc], addr);
    }

    float acc[9][4];
#pragma unroll
    for (int i = 0; i < 9; i++)
#pragma unroll
        for (int r = 0; r < 4; r++) acc[i][r] = 0.f;
    float m0 = -1e30f, m1 = -1e30f;

    const int NT = SEQ / 64;

#pragma unroll 1
    for (int kt = 0; kt < NT; kt++) {
        const uint32_t cur = sb + FA_STAGE0 + (kt & 1) * FA_STAGE_B;
        if (kt + 1 < NT) {
            load_kv(kt + 1, sb + FA_STAGE0 + ((kt + 1) & 1) * FA_STAGE_B);
            CP_ASYNC_WAIT(1);
        } else {
            CP_ASYNC_WAIT(0);
        }
        __syncthreads();

        float s[8][4];
#pragma unroll
        for (int nt = 0; nt < 8; nt++)
#pragma unroll
            for (int r = 0; r < 4; r++) s[nt][r] = 0.f;

#pragma unroll
        for (int kc = 0; kc < 4; kc++) {
#pragma unroll
            for (int kg = 0; kg < 4; kg++) {
                uint32_t ka = cur + FA_STG_K + (uint32_t)(kg * 16 + (lane & 15)) * FA_KSTRIDE
                              + kc * 32 + (lane >> 4) * 16;
                uint32_t kh4[4];
                LDMATRIX_X4(kh4, ka);
                mma_f16(s[kg * 2 + 0], qfh[kc], kh4[0], kh4[2]);
                mma_f16(s[kg * 2 + 1], qfh[kc], kh4[1], kh4[3]);
            }
        }

        float mx0 = -1e30f, mx1 = -1e30f;
#pragma unroll
        for (int nt = 0; nt < 8; nt++) {
            mx0 = fmaxf(mx0, fmaxf(s[nt][0], s[nt][1]));
            mx1 = fmaxf(mx1, fmaxf(s[nt][2], s[nt][3]));
        }
        mx0 = fmaxf(mx0, __shfl_xor_sync(FULL, mx0, 1));
        mx0 = fmaxf(mx0, __shfl_xor_sync(FULL, mx0, 2));
        mx1 = fmaxf(mx1, __shfl_xor_sync(FULL, mx1, 1));
        mx1 = fmaxf(mx1, __shfl_xor_sync(FULL, mx1, 2));
        float nm0 = fmaxf(m0, mx0), nm1 = fmaxf(m1, mx1);
        float corr0 = ex2f(m0 - nm0), corr1 = ex2f(m1 - nm1);
        m0 = nm0; m1 = nm1;

#pragma unroll
        for (int nt = 0; nt < 8; nt++) {
            uint32_t p0 = ex2_pk(s[nt][0] - nm0, s[nt][1] - nm0);
            uint32_t p1 = ex2_pk(s[nt][2] - nm1, s[nt][3] - nm1);
            s[nt][0] = __uint_as_float(p0);
            s[nt][1] = __uint_as_float(p1);
        }
#pragma unroll
        for (int j = 0; j < 9; j++) {
            acc[j][0] *= corr0; acc[j][1] *= corr0;
            acc[j][2] *= corr1; acc[j][3] *= corr1;
        }

#pragma unroll
        for (int kk = 0; kk < 4; kk++) {
            uint32_t pa[4] = { __float_as_uint(s[2 * kk][0]),
                               __float_as_uint(s[2 * kk][1]),
                               __float_as_uint(s[2 * kk + 1][0]),
                               __float_as_uint(s[2 * kk + 1][1]) };
#pragma unroll
            for (int vp = 0; vp < 5; vp++) {
                uint32_t va = cur + FA_STG_V + (uint32_t)(kk * 16 + (lane & 15)) * FA_VSTRIDE
                              + vp * 32 + (lane >> 4) * 16;
                uint32_t vh4[4];
                LDMATRIX_X4_T(vh4, va);
                if (vp < 4) {
                    mma_f16(acc[vp * 2], pa, vh4[0], vh4[1]);
                    mma_f16(acc[vp * 2 + 1], pa, vh4[2], vh4[3]);
                } else {
                    mma_f16(acc[8], pa, vh4[0], vh4[1]);
                }
            }
        }
        __syncthreads();
    }

    float l0 = __shfl_sync(FULL, acc[8][0], lane & 28);
    float l1 = __shfl_sync(FULL, acc[8][2], lane & 28);
    float inv0 = 1.0f / l0, inv1 = 1.0f / l1;

    int gr0 = q0 + wid * 16 + (lane >> 2);
#pragma unroll
    for (int nt = 0; nt < 8; nt++) {
        int col = h * HD + nt * 8 + (lane & 3) * 2;
        size_t i0 = (size_t)(b * SEQ + gr0) * CDIM + col;
        size_t i1 = (size_t)(b * SEQ + gr0 + 8) * CDIM + col;
        __half2 o0 = {__float2half_rn(acc[nt][0] * inv0),
                      __float2half_rn(acc[nt][1] * inv0)};
        __half2 o1 = {__float2half_rn(acc[nt][2] * inv1),
                      __float2half_rn(acc[nt][3] * inv1)};
        *(__half2*)&O[i0] = o0;
        *(__half2*)&O[i1] = o1;
    }
}

// =================================================================
// launcher
// =================================================================
extern "C" void kernel_launch(void* const* d_in, const int* in_sizes, int n_in,
                              void* d_out, int out_size)
{
    const float* x        = (const float*)d_in[0];
    const float* rope_cos = (const float*)d_in[1];
    const float* rope_sin = (const float*)d_in[2];
    const float* w_qkv    = (const float*)d_in[3];
    const float* w_proj   = (const float*)d_in[4];
    const float* b_proj   = (const float*)d_in[5];
    const float* q_norm_w = (const float*)d_in[6];
    const float* k_norm_w = (const float*)d_in[7];
    float* out = (float*)d_out;

    __half *qh, *kh, *vh;
    cudaGetSymbolAddress((void**)&qh, g_qh);
    cudaGetSymbolAddress((void**)&kh, g_kh);
    cudaGetSymbolAddress((void**)&vh, g_vh);
    __half *x16, *wq16, *wp16, *ao16;
    cudaGetSymbolAddress((void**)&x16,  g_x16);
    cudaGetSymbolAddress((void**)&wq16, g_wq16);
    cudaGetSymbolAddress((void**)&wp16, g_wp16);
    cudaGetSymbolAddress((void**)&ao16, g_ao16);

    cudaFuncSetAttribute(gemm_qkv_fused,
                         cudaFuncAttributeMaxDynamicSharedMemorySize, G1_SMEM_B);
    cudaFuncSetAttribute(gemm_proj,
                         cudaFuncAttributeMaxDynamicSharedMemorySize, G1_SMEM_B);
    cudaFuncSetAttribute(flash_attn_mma,
                         cudaFuncAttributeMaxDynamicSharedMemorySize, FA_SMEM);

    // 0) fp32 -> f16 conversions
    {
        size_t nx = (size_t)M_ROWS * KDIM;
        cvt_f16<<<(unsigned)(nx / 1024), 256>>>(x, x16, nx);
        size_t nwq = (size_t)QKV_N * KDIM;
        cvt_f16<<<(unsigned)(nwq / 1024), 256>>>(w_qkv, wq16, nwq);
        size_t nwp = (size_t)CDIM * KDIM;
        cvt_f16<<<(unsigned)(nwp / 1024), 256>>>(w_proj, wp16, nwp);
    }
    // 1) QKV projection with fused RMSNorm+RoPE+split -> f16 Q,K,V
    {
        dim3 grid(QKV_N / 128, M_ROWS / 128);
        gemm_qkv_fused<<<grid, 256, G1_SMEM_B>>>(
            x16, wq16, rope_cos, rope_sin, q_norm_w, k_norm_w,
            qh, kh, vh, M_ROWS, QKV_N, KDIM);
    }
    // 2) Flash attention (online-max) -> f16 attn output
    {
        dim3 grid(SEQ / 128, BATCH * HEADS);
        flash_attn_mma<<<grid, 256, FA_SMEM>>>(qh, kh, vh, ao16);
    }
    // 3) Output projection + bias -> f32
    {
        dim3 grid(CDIM / 128, M_ROWS / 128);
        gemm_proj<<<grid, 256, G1_SMEM_B>>>(
            ao16, wp16, b_proj, out, M_ROWS, CDIM, KDIM);
    }
}